// round 8
// baseline (speedup 1.0000x reference)
#include <cuda_runtime.h>
#include <math.h>

// Problem shapes (fixed by the dataset)
#define B  32
#define C  512
#define D  4096
#define H  128        // hidden
#define NROWS (B * C) // 16384

// Pool kernel tiling
#define PR 128        // rows per block (= threads per block)
#define PCH 64        // columns per chunk
#define NCH (D / PCH) // 64 chunks

// Scratch (no cudaMalloc allowed)
__device__ float g_pooled[B * C];
__device__ int   g_ord[B * C];

// ---------------------------------------------------------------------------
// Bit-faithful XLA-CPU vectorized expf (GenerateVF32Exp / old Eigen pexp):
// Horner polynomial, separate-rounded mul/add. For our domain |x| < 0.35,
// fx == 0 so the reduction is exact. (R4's fma variant and this one produce
// the identical flip set — exp is converged; kept in the most faithful form.)
// ---------------------------------------------------------------------------
__device__ __forceinline__ float xla_cpu_expf(float x) {
    const float exp_hi = 88.3762626647950f;
    const float exp_lo = -88.3762626647949f;
    const float LOG2EF = 1.44269504088896341f;
    const float C1 = 0.693359375f;
    const float C2 = -2.12194440e-4f;
    const float p0 = 1.9875691500e-4f;
    const float p1 = 1.3981999507e-3f;
    const float p2 = 8.3334519073e-3f;
    const float p3 = 4.1665795894e-2f;
    const float p4 = 1.6666665459e-1f;
    const float p5 = 5.0000001201e-1f;

    x = fminf(fmaxf(x, exp_lo), exp_hi);

    float fx = __fadd_rn(__fmul_rn(x, LOG2EF), 0.5f);
    fx = floorf(fx);

    float tmp = __fmul_rn(fx, C1);
    float z   = __fmul_rn(fx, C2);
    x = __fsub_rn(x, tmp);
    x = __fsub_rn(x, z);
    z = __fmul_rn(x, x);

    float y = p0;
    y = __fadd_rn(__fmul_rn(y, x), p1);
    y = __fadd_rn(__fmul_rn(y, x), p2);
    y = __fadd_rn(__fmul_rn(y, x), p3);
    y = __fadd_rn(__fmul_rn(y, x), p4);
    y = __fadd_rn(__fmul_rn(y, x), p5);
    y = __fadd_rn(__fmul_rn(y, z), x);
    y = __fadd_rn(y, 1.0f);

    int n = (int)fx;
    y = __fmul_rn(y, __int_as_float((n + 127) << 23));
    return y;
}

// ---------------------------------------------------------------------------
// Kernel A: pooled[row] = (sequential in-order fp32 sum of x[row][0..4095])
//                         * (1/4096)   [exact power-of-2 scale]
// Emulates XLA-CPU's non-reassociated scalar reduce bit-exactly.
// Each thread owns one row; chunks of 64 columns are staged through smem
// (coalesced float4 global loads, conflict-free transposed reads).
// tile layout [col][row] with row-stride 129: store bank (4*c4+j+r)%32 (2-way
// on stores only), load bank (i+t)%32 (conflict-free).
// ---------------------------------------------------------------------------
__global__ void __launch_bounds__(PR) pool_kernel(const float* __restrict__ x) {
    __shared__ float tile[PCH][PR + 1];   // [64][129] ≈ 33 KB

    const int tid  = threadIdx.x;
    const int base = blockIdx.x * PR;     // first row of this block
    const float4* __restrict__ x4 = reinterpret_cast<const float4*>(x);

    float acc = 0.f;

    for (int ch = 0; ch < NCH; ++ch) {
        // Stage chunk: rows [base, base+128), cols [ch*64, ch*64+64)
        // 128 rows * 16 float4 = 2048 float4; 16 per thread, coalesced.
#pragma unroll
        for (int it = 0; it < 16; ++it) {
            const int g  = tid + it * PR;   // 0..2047
            const int r  = g >> 4;          // row within block
            const int c4 = g & 15;          // float4 within chunk
            float4 v = x4[(size_t)(base + r) * (D / 4) + ch * 16 + c4];
            const int c = c4 * 4;
            tile[c + 0][r] = v.x;
            tile[c + 1][r] = v.y;
            tile[c + 2][r] = v.z;
            tile[c + 3][r] = v.w;
        }
        __syncthreads();

        // Strict sequential accumulation, in column order.
#pragma unroll
        for (int i = 0; i < PCH; ++i)
            acc = __fadd_rn(acc, tile[i][tid]);
        __syncthreads();
    }

    g_pooled[base + tid] = __fmul_rn(acc, (1.0f / (float)D));
}

// ---------------------------------------------------------------------------
// Kernel B: per batch-item (grid = 32, block = 512), fp32 throughout:
//   - dots: single fp32 accumulator, sequential ascending k, fmaf chain
//   - bias added AFTER the dot (separate fadd); LeakyReLU = 0.01f * h
//   - sigmoid = 1 / (1 + xla_cpu_expf(-z)), IEEE div.rn
// Then stable argsort (score desc, idx asc) via bitonic sort on a strict key.
// ---------------------------------------------------------------------------
__global__ void __launch_bounds__(512) mlp_sort_kernel(
    const float* __restrict__ W1, const float* __restrict__ b1,
    const float* __restrict__ W2, const float* __restrict__ b2) {
    const int b   = blockIdx.x;
    const int tid = threadIdx.x;

    __shared__ float ps[C];
    __shared__ float hs[H];
    __shared__ float ss[C];
    __shared__ int   si[C];

    ps[tid] = g_pooled[b * C + tid];
    __syncthreads();

    if (tid < H) {
        const float* __restrict__ w = W1 + tid * C;
        float acc = 0.f;
        for (int k = 0; k < C; k++) acc = fmaf(w[k], ps[k], acc);
        acc = __fadd_rn(acc, b1[tid]);
        hs[tid] = (acc >= 0.f) ? acc : __fmul_rn(0.01f, acc);
    }
    __syncthreads();

    {
        const float* __restrict__ w = W2 + tid * H;
        float acc = 0.f;
        for (int k = 0; k < H; k++) acc = fmaf(w[k], hs[k], acc);
        acc = __fadd_rn(acc, b2[tid]);
        float e = xla_cpu_expf(-acc);
        ss[tid] = __fdiv_rn(1.0f, __fadd_rn(1.0f, e));
        si[tid] = tid;
    }
    __syncthreads();

    // Bitonic sort, 512 elems, key = (score desc, idx asc) — strict total
    // order, equivalent to stable descending argsort.
    for (int k = 2; k <= C; k <<= 1) {
        for (int j = k >> 1; j > 0; j >>= 1) {
            const int i   = tid;
            const int ixj = i ^ j;
            if (ixj > i) {
                const float a_s = ss[i],  b_s = ss[ixj];
                const int   a_i = si[i],  b_i = si[ixj];
                const bool b_precedes_a = (b_s > a_s) || (b_s == a_s && b_i < a_i);
                const bool a_precedes_b = (a_s > b_s) || (a_s == b_s && a_i < b_i);
                const bool up = ((i & k) == 0);
                const bool do_swap = up ? b_precedes_a : a_precedes_b;
                if (do_swap) {
                    ss[i] = b_s; ss[ixj] = a_s;
                    si[i] = b_i; si[ixj] = a_i;
                }
            }
            __syncthreads();
        }
    }

    g_ord[b * C + tid] = si[tid];
}

// ---------------------------------------------------------------------------
// Kernel C: out[b,c,:] = x[b,c,:] + x[b, ord[b][c], :]
// b-major grid: concurrent blocks share one 8 MiB batch slice (<< 126 MB L2)
// so the gathered second read hits L2, not DRAM.
// ---------------------------------------------------------------------------
__global__ void __launch_bounds__(256) shuffle_add_kernel(
    const float* __restrict__ x, float* __restrict__ out) {
    const int row = blockIdx.x;          // b*512 + c
    const int b   = row >> 9;
    const int src = g_ord[row];

    const float4* __restrict__ xa =
        reinterpret_cast<const float4*>(x + (size_t)row * D);
    const float4* __restrict__ xb =
        reinterpret_cast<const float4*>(x + ((size_t)(b << 9) + src) * D);
    float4* __restrict__ o = reinterpret_cast<float4*>(out + (size_t)row * D);

#pragma unroll 4
    for (int i = threadIdx.x; i < D / 4; i += 256) {
        float4 a = xa[i];
        float4 g = xb[i];
        a.x += g.x; a.y += g.y; a.z += g.z; a.w += g.w;
        o[i] = a;
    }
}

// ---------------------------------------------------------------------------
extern "C" void kernel_launch(void* const* d_in, const int* in_sizes, int n_in,
                              void* d_out, int out_size) {
    const float* x  = (const float*)d_in[0];
    const float* W1 = (const float*)d_in[1];
    const float* b1 = (const float*)d_in[2];
    const float* W2 = (const float*)d_in[3];
    const float* b2 = (const float*)d_in[4];
    float* out = (float*)d_out;

    pool_kernel<<<NROWS / PR, PR>>>(x);
    mlp_sort_kernel<<<B, 512>>>(W1, b1, W2, b2);
    shuffle_add_kernel<<<NROWS, 256>>>(x, out);
}

// round 9
// speedup vs baseline: 1.0236x; 1.0236x over previous
#include <cuda_runtime.h>
#include <math.h>

// Problem shapes (fixed by the dataset)
#define B  32
#define C  512
#define D  4096
#define H  128        // hidden
#define NROWS (B * C) // 16384

// Pool kernel tiling
#define PR   128      // rows per block (= threads per block)
#define PCH  32       // columns per chunk
#define NCH  (D / PCH)        // 128 chunks
#define F4PT (PR * PCH / 4 / PR) // float4 loads per thread per chunk = 8

// Scratch (no cudaMalloc allowed)
__device__ float g_pooled[B * C];
__device__ int   g_ord[B * C];

// ---------------------------------------------------------------------------
// Bit-faithful XLA-CPU vectorized expf (GenerateVF32Exp / old Eigen pexp):
// Horner polynomial, separate-rounded mul/add. PROVEN: rel_err == 0.0.
// DO NOT MODIFY.
// ---------------------------------------------------------------------------
__device__ __forceinline__ float xla_cpu_expf(float x) {
    const float exp_hi = 88.3762626647950f;
    const float exp_lo = -88.3762626647949f;
    const float LOG2EF = 1.44269504088896341f;
    const float C1 = 0.693359375f;
    const float C2 = -2.12194440e-4f;
    const float p0 = 1.9875691500e-4f;
    const float p1 = 1.3981999507e-3f;
    const float p2 = 8.3334519073e-3f;
    const float p3 = 4.1665795894e-2f;
    const float p4 = 1.6666665459e-1f;
    const float p5 = 5.0000001201e-1f;

    x = fminf(fmaxf(x, exp_lo), exp_hi);

    float fx = __fadd_rn(__fmul_rn(x, LOG2EF), 0.5f);
    fx = floorf(fx);

    float tmp = __fmul_rn(fx, C1);
    float z   = __fmul_rn(fx, C2);
    x = __fsub_rn(x, tmp);
    x = __fsub_rn(x, z);
    z = __fmul_rn(x, x);

    float y = p0;
    y = __fadd_rn(__fmul_rn(y, x), p1);
    y = __fadd_rn(__fmul_rn(y, x), p2);
    y = __fadd_rn(__fmul_rn(y, x), p3);
    y = __fadd_rn(__fmul_rn(y, x), p4);
    y = __fadd_rn(__fmul_rn(y, x), p5);
    y = __fadd_rn(__fmul_rn(y, z), x);
    y = __fadd_rn(y, 1.0f);

    int n = (int)fx;
    y = __fmul_rn(y, __int_as_float((n + 127) << 23));
    return y;
}

// ---------------------------------------------------------------------------
// Kernel A: pooled[row] = (strict sequential fp32 sum over d) * (1/4096).
// SAME ADDITION ORDER as round 8 (bit-exact, rel_err==0.0) — only the
// scheduling changed: double-buffered smem tiles + register prefetch so the
// next chunk's global loads overlap the current chunk's serial FADD chain.
//   - global loads: coalesced float4 (full-line wavefronts)
//   - smem stores: bank = (4*c4 + j + r) % 32 -> conflict-free (verified)
//   - smem loads:  bank = (i + tid) % 32      -> conflict-free
// ---------------------------------------------------------------------------
__global__ void __launch_bounds__(PR) pool_kernel(const float* __restrict__ x) {
    __shared__ float tile[2][PCH][PR + 1];   // 2 * 32 * 129 * 4B = 33 KB

    const int tid  = threadIdx.x;
    const int base = blockIdx.x * PR;
    const float4* __restrict__ x4 = reinterpret_cast<const float4*>(x);

    float4 buf[F4PT];   // 8 float4 = prefetch staging (32 regs)

    // Prologue: load + stage chunk 0
#pragma unroll
    for (int it = 0; it < F4PT; ++it) {
        const int g  = tid + it * PR;   // 0..1023
        const int r  = g >> 3;          // row within block (128 rows x 8 f4)
        const int c4 = g & 7;           // float4 within chunk
        buf[it] = x4[(size_t)(base + r) * (D / 4) + c4];
    }
#pragma unroll
    for (int it = 0; it < F4PT; ++it) {
        const int g = tid + it * PR;
        const int r = g >> 3;
        const int c = (g & 7) * 4;
        tile[0][c + 0][r] = buf[it].x;
        tile[0][c + 1][r] = buf[it].y;
        tile[0][c + 2][r] = buf[it].z;
        tile[0][c + 3][r] = buf[it].w;
    }
    __syncthreads();

    float acc = 0.f;
    for (int ch = 0; ch < NCH; ++ch) {
        const int cur = ch & 1;
        const int nxt = cur ^ 1;

        // Prefetch chunk ch+1 into registers (independent of the add chain;
        // LDGs stay outstanding across the FADD loop below).
        if (ch + 1 < NCH) {
#pragma unroll
            for (int it = 0; it < F4PT; ++it) {
                const int g  = tid + it * PR;
                const int r  = g >> 3;
                const int c4 = g & 7;
                buf[it] = x4[(size_t)(base + r) * (D / 4)
                             + (size_t)(ch + 1) * (PCH / 4) + c4];
            }
        }

        // Strict sequential accumulation over this chunk's 32 columns.
#pragma unroll
        for (int i = 0; i < PCH; ++i)
            acc = __fadd_rn(acc, tile[cur][i][tid]);

        // Stage prefetched chunk into the other buffer (consumes LDG results).
        if (ch + 1 < NCH) {
#pragma unroll
            for (int it = 0; it < F4PT; ++it) {
                const int g = tid + it * PR;
                const int r = g >> 3;
                const int c = (g & 7) * 4;
                tile[nxt][c + 0][r] = buf[it].x;
                tile[nxt][c + 1][r] = buf[it].y;
                tile[nxt][c + 2][r] = buf[it].z;
                tile[nxt][c + 3][r] = buf[it].w;
            }
        }
        __syncthreads();
    }

    g_pooled[base + tid] = __fmul_rn(acc, (1.0f / (float)D));
}

// ---------------------------------------------------------------------------
// Kernel B: per batch-item (grid = 32, block = 512), fp32 throughout.
// PROVEN bit-exact (rel_err==0.0). DO NOT MODIFY ARITHMETIC.
// ---------------------------------------------------------------------------
__global__ void __launch_bounds__(512) mlp_sort_kernel(
    const float* __restrict__ W1, const float* __restrict__ b1,
    const float* __restrict__ W2, const float* __restrict__ b2) {
    const int b   = blockIdx.x;
    const int tid = threadIdx.x;

    __shared__ float ps[C];
    __shared__ float hs[H];
    __shared__ float ss[C];
    __shared__ int   si[C];

    ps[tid] = g_pooled[b * C + tid];
    __syncthreads();

    if (tid < H) {
        const float* __restrict__ w = W1 + tid * C;
        float acc = 0.f;
        for (int k = 0; k < C; k++) acc = fmaf(w[k], ps[k], acc);
        acc = __fadd_rn(acc, b1[tid]);
        hs[tid] = (acc >= 0.f) ? acc : __fmul_rn(0.01f, acc);
    }
    __syncthreads();

    {
        const float* __restrict__ w = W2 + tid * H;
        float acc = 0.f;
        for (int k = 0; k < H; k++) acc = fmaf(w[k], hs[k], acc);
        acc = __fadd_rn(acc, b2[tid]);
        float e = xla_cpu_expf(-acc);
        ss[tid] = __fdiv_rn(1.0f, __fadd_rn(1.0f, e));
        si[tid] = tid;
    }
    __syncthreads();

    // Bitonic sort, 512 elems, key = (score desc, idx asc).
    for (int k = 2; k <= C; k <<= 1) {
        for (int j = k >> 1; j > 0; j >>= 1) {
            const int i   = tid;
            const int ixj = i ^ j;
            if (ixj > i) {
                const float a_s = ss[i],  b_s = ss[ixj];
                const int   a_i = si[i],  b_i = si[ixj];
                const bool b_precedes_a = (b_s > a_s) || (b_s == a_s && b_i < a_i);
                const bool a_precedes_b = (a_s > b_s) || (a_s == b_s && a_i < b_i);
                const bool up = ((i & k) == 0);
                const bool do_swap = up ? b_precedes_a : a_precedes_b;
                if (do_swap) {
                    ss[i] = b_s; ss[ixj] = a_s;
                    si[i] = b_i; si[ixj] = a_i;
                }
            }
            __syncthreads();
        }
    }

    g_ord[b * C + tid] = si[tid];
}

// ---------------------------------------------------------------------------
// Kernel C: out[b,c,:] = x[b,c,:] + x[b, ord[b][c], :]
// b-major grid: concurrent blocks share one 8 MiB batch slice (<< 126 MB L2)
// so the gathered second read hits L2, not DRAM.
// ---------------------------------------------------------------------------
__global__ void __launch_bounds__(256) shuffle_add_kernel(
    const float* __restrict__ x, float* __restrict__ out) {
    const int row = blockIdx.x;          // b*512 + c
    const int b   = row >> 9;
    const int src = g_ord[row];

    const float4* __restrict__ xa =
        reinterpret_cast<const float4*>(x + (size_t)row * D);
    const float4* __restrict__ xb =
        reinterpret_cast<const float4*>(x + ((size_t)(b << 9) + src) * D);
    float4* __restrict__ o = reinterpret_cast<float4*>(out + (size_t)row * D);

#pragma unroll 4
    for (int i = threadIdx.x; i < D / 4; i += 256) {
        float4 a = xa[i];
        float4 g = xb[i];
        a.x += g.x; a.y += g.y; a.z += g.z; a.w += g.w;
        o[i] = a;
    }
}

// ---------------------------------------------------------------------------
extern "C" void kernel_launch(void* const* d_in, const int* in_sizes, int n_in,
                              void* d_out, int out_size) {
    const float* x  = (const float*)d_in[0];
    const float* W1 = (const float*)d_in[1];
    const float* b1 = (const float*)d_in[2];
    const float* W2 = (const float*)d_in[3];
    const float* b2 = (const float*)d_in[4];
    float* out = (float*)d_out;

    pool_kernel<<<NROWS / PR, PR>>>(x);
    mlp_sort_kernel<<<B, 512>>>(W1, b1, W2, b2);
    shuffle_add_kernel<<<NROWS, 256>>>(x, out);
}